// round 1
// baseline (speedup 1.0000x reference)
#include <cuda_runtime.h>
#include <math.h>

#define BT 256   // threads per row-block

// Scratch for per-row losses (allocation-free rule: __device__ global).
__device__ float g_row_loss[65536];

__global__ void __launch_bounds__(BT) row_loss_kernel(
    const float* __restrict__ x,
    const int*   __restrict__ tgt,
    int N, int V, float log_scale)
{
    const int row = blockIdx.x;
    if (row >= N) return;
    const float* __restrict__ r = x + (size_t)row * (size_t)V;
    const int tid = threadIdx.x;
    const float L2E = 1.4426950408889634f;  // log2(e)

    float m = -3.402823466e38f;
    float s = 0.0f;

    // Main loop: 4 coalesced loads per iteration, one chunk-max so the
    // rescale of s happens rarely (keeps the MUFU count at ~1/element).
    const int quad     = 4 * BT;
    const int quad_end = (V / quad) * quad;
    for (int base = 0; base < quad_end; base += quad) {
        float x0 = r[base + tid];
        float x1 = r[base + tid +     BT];
        float x2 = r[base + tid + 2 * BT];
        float x3 = r[base + tid + 3 * BT];
        float c = fmaxf(fmaxf(x0, x1), fmaxf(x2, x3));
        if (c > m) { s *= exp2f((m - c) * L2E); m = c; }
        s += exp2f((x0 - m) * L2E);
        s += exp2f((x1 - m) * L2E);
        s += exp2f((x2 - m) * L2E);
        s += exp2f((x3 - m) * L2E);
    }
    // Remainder (V % 1024 elements), still coalesced.
    for (int i = quad_end + tid; i < V; i += BT) {
        float xv = r[i];
        if (xv > m) { s *= exp2f((m - xv) * L2E); m = xv; }
        s += exp2f((xv - m) * L2E);
    }

    // Warp-level (m, s) merge.
    #pragma unroll
    for (int off = 16; off > 0; off >>= 1) {
        float m2 = __shfl_xor_sync(0xffffffffu, m, off);
        float s2 = __shfl_xor_sync(0xffffffffu, s, off);
        float nm = fmaxf(m, m2);
        s = s * exp2f((m - nm) * L2E) + s2 * exp2f((m2 - nm) * L2E);
        m = nm;
    }

    __shared__ float sm[BT / 32];
    __shared__ float ss[BT / 32];
    const int warp = tid >> 5;
    const int lane = tid & 31;
    if (lane == 0) { sm[warp] = m; ss[warp] = s; }
    __syncthreads();

    if (warp == 0) {
        m = (lane < BT / 32) ? sm[lane] : -3.402823466e38f;
        s = (lane < BT / 32) ? ss[lane] : 0.0f;
        #pragma unroll
        for (int off = (BT / 32) / 2; off > 0; off >>= 1) {
            float m2 = __shfl_xor_sync(0xffffffffu, m, off);
            float s2 = __shfl_xor_sync(0xffffffffu, s, off);
            float nm = fmaxf(m, m2);
            s = s * exp2f((m - nm) * L2E) + s2 * exp2f((m2 - nm) * L2E);
            m = nm;
        }
        if (lane == 0) {
            float lse = m + logf(s);                 // log-sum-exp of the row
            float xt  = r[tgt[row]];                 // logit at target class
            // loss_row = -(x_t - lse + log_scale)
            g_row_loss[row] = lse - xt - log_scale;
        }
    }
}

__global__ void __launch_bounds__(1024) final_reduce_kernel(
    float* __restrict__ out, int N)
{
    float acc = 0.0f;
    for (int i = threadIdx.x; i < N; i += 1024)
        acc += g_row_loss[i];

    #pragma unroll
    for (int off = 16; off > 0; off >>= 1)
        acc += __shfl_xor_sync(0xffffffffu, acc, off);

    __shared__ float w[32];
    const int warp = threadIdx.x >> 5;
    const int lane = threadIdx.x & 31;
    if (lane == 0) w[warp] = acc;
    __syncthreads();
    if (warp == 0) {
        acc = w[lane];   // 32 warps -> all 32 slots valid
        #pragma unroll
        for (int off = 16; off > 0; off >>= 1)
            acc += __shfl_xor_sync(0xffffffffu, acc, off);
        if (lane == 0)
            out[0] = acc / (float)N;
    }
}

extern "C" void kernel_launch(void* const* d_in, const int* in_sizes, int n_in,
                              void* d_out, int out_size)
{
    const float* x   = (const float*)d_in[0];
    const int*   tgt = (const int*)d_in[1];
    float*       out = (float*)d_out;

    const int N = in_sizes[1];              // 4096 rows
    const int V = in_sizes[0] / N;          // 50257 classes

    const float ALPHA = 0.154f;
    const float scale = 1.0f - ALPHA + ALPHA / (float)V;
    const float log_scale = logf(scale);

    row_loss_kernel<<<N, BT>>>(x, tgt, N, V, log_scale);
    final_reduce_kernel<<<1, 1024>>>(out, N);
}

// round 2
// speedup vs baseline: 1.0135x; 1.0135x over previous
#include <cuda_runtime.h>
#include <math.h>
#include <stdint.h>

#define BT 256   // threads per row-block

// Scratch (allocation-free rule: __device__ globals).
__device__ float        g_row_loss[65536];
__device__ unsigned int g_done = 0;

__global__ void __launch_bounds__(BT) sce_fused_kernel(
    const float* __restrict__ x,
    const int*   __restrict__ tgt,
    int N, int V, float log_scale,
    float* __restrict__ out)
{
    const int row = blockIdx.x;
    const float* __restrict__ r = x + (size_t)row * (size_t)V;
    const int tid = threadIdx.x;
    const float L2E = 1.4426950408889634f;  // log2(e)

    float m  = -3.402823466e38f;   // running max
    float mL = -3.402823466e38f;   // m * log2(e)
    float s  = 0.0f;               // sum of 2^(x*L2E - mL)

    // ---- Peel to 16B alignment (row stride is 4 mod 16, rows alternate). ----
    int align = (int)(((uintptr_t)r) & 15);
    int peel  = ((16 - align) & 15) >> 2;          // 0..3 floats
    if (peel > V) peel = V;
    if (tid < peel) {
        float xv = r[tid];
        m = xv; mL = xv * L2E; s = 1.0f;
    }

    // ---- Main vectorized stream: 2x float4 per thread-iteration (8 elems). ----
    const float4* __restrict__ rv = (const float4*)(r + peel);
    const int nv = (V - peel) >> 2;                // float4 count
    int i = tid;
    for (; i + BT < nv; i += 2 * BT) {
        float4 a = rv[i];
        float4 b = rv[i + BT];
        float c = fmaxf(fmaxf(fmaxf(a.x, a.y), fmaxf(a.z, a.w)),
                        fmaxf(fmaxf(b.x, b.y), fmaxf(b.z, b.w)));
        if (c > m) { float cL = c * L2E; s *= exp2f(mL - cL); m = c; mL = cL; }
        s += exp2f(fmaf(a.x, L2E, -mL));
        s += exp2f(fmaf(a.y, L2E, -mL));
        s += exp2f(fmaf(a.z, L2E, -mL));
        s += exp2f(fmaf(a.w, L2E, -mL));
        s += exp2f(fmaf(b.x, L2E, -mL));
        s += exp2f(fmaf(b.y, L2E, -mL));
        s += exp2f(fmaf(b.z, L2E, -mL));
        s += exp2f(fmaf(b.w, L2E, -mL));
    }
    for (; i < nv; i += BT) {
        float4 a = rv[i];
        float c = fmaxf(fmaxf(a.x, a.y), fmaxf(a.z, a.w));
        if (c > m) { float cL = c * L2E; s *= exp2f(mL - cL); m = c; mL = cL; }
        s += exp2f(fmaf(a.x, L2E, -mL));
        s += exp2f(fmaf(a.y, L2E, -mL));
        s += exp2f(fmaf(a.z, L2E, -mL));
        s += exp2f(fmaf(a.w, L2E, -mL));
    }
    // ---- Scalar tail. ----
    for (int j = peel + 4 * nv + tid; j < V; j += BT) {
        float xv = r[j];
        if (xv > m) { float cL = xv * L2E; s *= exp2f(mL - cL); m = xv; mL = cL; }
        s += exp2f(fmaf(xv, L2E, -mL));
    }

    // ---- Warp-level (m, s) merge. ----
    #pragma unroll
    for (int off = 16; off > 0; off >>= 1) {
        float m2 = __shfl_xor_sync(0xffffffffu, m, off);
        float s2 = __shfl_xor_sync(0xffffffffu, s, off);
        float nm = fmaxf(m, m2);
        s = s * exp2f((m - nm) * L2E) + s2 * exp2f((m2 - nm) * L2E);
        m = nm;
    }

    __shared__ float sm[BT / 32];
    __shared__ float ss[BT / 32];
    __shared__ int   s_last;
    const int warp = tid >> 5;
    const int lane = tid & 31;
    if (lane == 0) { sm[warp] = m; ss[warp] = s; }
    __syncthreads();

    if (warp == 0) {
        m = (lane < BT / 32) ? sm[lane] : -3.402823466e38f;
        s = (lane < BT / 32) ? ss[lane] : 0.0f;
        #pragma unroll
        for (int off = (BT / 32) / 2; off > 0; off >>= 1) {
            float m2 = __shfl_xor_sync(0xffffffffu, m, off);
            float s2 = __shfl_xor_sync(0xffffffffu, s, off);
            float nm = fmaxf(m, m2);
            s = s * exp2f((m - nm) * L2E) + s2 * exp2f((m2 - nm) * L2E);
            m = nm;
        }
        if (lane == 0) {
            float lse = m + logf(s);
            float xt  = r[tgt[row]];
            g_row_loss[row] = lse - xt - log_scale;   // -(x_t - lse + log_scale)
            __threadfence();
            unsigned int v = atomicAdd(&g_done, 1u);
            s_last = (v == (unsigned int)(N - 1)) ? 1 : 0;
        }
    }
    __syncthreads();

    // ---- Last block to finish performs the deterministic final mean. ----
    if (s_last) {
        __threadfence();   // acquire all blocks' g_row_loss stores
        float acc = 0.0f;
        for (int j = tid; j < N; j += BT)
            acc += g_row_loss[j];

        #pragma unroll
        for (int off = 16; off > 0; off >>= 1)
            acc += __shfl_xor_sync(0xffffffffu, acc, off);

        __shared__ float w[BT / 32];
        if (lane == 0) w[warp] = acc;
        __syncthreads();
        if (warp == 0) {
            acc = (lane < BT / 32) ? w[lane] : 0.0f;
            #pragma unroll
            for (int off = (BT / 32) / 2; off > 0; off >>= 1)
                acc += __shfl_xor_sync(0xffffffffu, acc, off);
            if (lane == 0) {
                out[0] = acc / (float)N;
                g_done = 0;   // reset for next graph replay
            }
        }
    }
}

extern "C" void kernel_launch(void* const* d_in, const int* in_sizes, int n_in,
                              void* d_out, int out_size)
{
    const float* x   = (const float*)d_in[0];
    const int*   tgt = (const int*)d_in[1];
    float*       out = (float*)d_out;

    const int N = in_sizes[1];              // 4096 rows
    const int V = in_sizes[0] / N;          // 50257 classes

    const float ALPHA = 0.154f;
    const float scale = 1.0f - ALPHA + ALPHA / (float)V;
    const float log_scale = logf(scale);

    sce_fused_kernel<<<N, BT>>>(x, tgt, N, V, log_scale, out);
}

// round 4
// speedup vs baseline: 1.0474x; 1.0334x over previous
#include <cuda_runtime.h>
#include <math.h>
#include <stdint.h>

#define BT 256   // threads per row-block

// Scratch (allocation-free rule: __device__ globals).
__device__ float        g_row_loss[65536];
__device__ unsigned int g_done = 0;

__device__ __forceinline__ float max4(float4 a) {
    return fmaxf(fmaxf(a.x, a.y), fmaxf(a.z, a.w));
}

__global__ void __launch_bounds__(BT) sce_fused_kernel(
    const float* __restrict__ x,
    const int*   __restrict__ tgt,
    int N, int V, float log_scale,
    float* __restrict__ out)
{
    const int row = blockIdx.x;
    const float* __restrict__ r = x + (size_t)row * (size_t)V;
    const int tid = threadIdx.x;
    const float L2E = 1.4426950408889634f;  // log2(e)

    float m  = -3.402823466e38f;   // running max
    float mL = -3.402823466e38f;   // m * log2(e)
    float s0 = 0.0f, s1 = 0.0f, s2 = 0.0f, s3 = 0.0f;

    // ---- Peel to 16B alignment (row stride is 4 mod 16; rows alternate). ----
    int align = (int)(((uintptr_t)r) & 15);
    int peel  = ((16 - align) & 15) >> 2;          // 0..3 floats
    if (peel > V) peel = V;
    if (tid < peel) {
        float xv = r[tid];
        m = xv; mL = xv * L2E; s0 = 1.0f;
    }

    // ---- Main stream: 4x float4 per iteration (16 elems/thread). ----
    const float4* __restrict__ rv = (const float4*)(r + peel);
    const int nv = (V - peel) >> 2;                // float4 count
    int i = tid;
    for (; i + 3 * BT < nv; i += 4 * BT) {
        float4 a = __ldcs(&rv[i]);
        float4 b = __ldcs(&rv[i +     BT]);
        float4 c4 = __ldcs(&rv[i + 2 * BT]);
        float4 d = __ldcs(&rv[i + 3 * BT]);
        float c = fmaxf(fmaxf(max4(a), max4(b)), fmaxf(max4(c4), max4(d)));
        if (c > m) {
            float cL = c * L2E;
            float f  = exp2f(mL - cL);
            s0 *= f; s1 *= f; s2 *= f; s3 *= f;
            m = c; mL = cL;
        }
        s0 += exp2f(fmaf(a.x, L2E, -mL));
        s1 += exp2f(fmaf(a.y, L2E, -mL));
        s2 += exp2f(fmaf(a.z, L2E, -mL));
        s3 += exp2f(fmaf(a.w, L2E, -mL));
        s0 += exp2f(fmaf(b.x, L2E, -mL));
        s1 += exp2f(fmaf(b.y, L2E, -mL));
        s2 += exp2f(fmaf(b.z, L2E, -mL));
        s3 += exp2f(fmaf(b.w, L2E, -mL));
        s0 += exp2f(fmaf(c4.x, L2E, -mL));
        s1 += exp2f(fmaf(c4.y, L2E, -mL));
        s2 += exp2f(fmaf(c4.z, L2E, -mL));
        s3 += exp2f(fmaf(c4.w, L2E, -mL));
        s0 += exp2f(fmaf(d.x, L2E, -mL));
        s1 += exp2f(fmaf(d.y, L2E, -mL));
        s2 += exp2f(fmaf(d.z, L2E, -mL));
        s3 += exp2f(fmaf(d.w, L2E, -mL));
    }
    for (; i < nv; i += BT) {
        float4 a = __ldcs(&rv[i]);
        float c = max4(a);
        if (c > m) {
            float cL = c * L2E;
            float f  = exp2f(mL - cL);
            s0 *= f; s1 *= f; s2 *= f; s3 *= f;
            m = c; mL = cL;
        }
        s0 += exp2f(fmaf(a.x, L2E, -mL));
        s1 += exp2f(fmaf(a.y, L2E, -mL));
        s2 += exp2f(fmaf(a.z, L2E, -mL));
        s3 += exp2f(fmaf(a.w, L2E, -mL));
    }
    // ---- Scalar tail. ----
    for (int j = peel + 4 * nv + tid; j < V; j += BT) {
        float xv = r[j];
        if (xv > m) {
            float cL = xv * L2E;
            float f  = exp2f(mL - cL);
            s0 *= f; s1 *= f; s2 *= f; s3 *= f;
            m = xv; mL = cL;
        }
        s0 += exp2f(fmaf(xv, L2E, -mL));
    }

    float s = (s0 + s1) + (s2 + s3);

    // ---- Warp-level (m, s) merge. ----
    #pragma unroll
    for (int off = 16; off > 0; off >>= 1) {
        float m2 = __shfl_xor_sync(0xffffffffu, m, off);
        float sx = __shfl_xor_sync(0xffffffffu, s, off);
        float nm = fmaxf(m, m2);
        s = s * exp2f((m - nm) * L2E) + sx * exp2f((m2 - nm) * L2E);
        m = nm;
    }

    __shared__ float sm[BT / 32];
    __shared__ float ss[BT / 32];
    __shared__ int   s_last;
    const int warp = tid >> 5;
    const int lane = tid & 31;
    if (lane == 0) { sm[warp] = m; ss[warp] = s; }
    __syncthreads();

    if (warp == 0) {
        m = (lane < BT / 32) ? sm[lane] : -3.402823466e38f;
        s = (lane < BT / 32) ? ss[lane] : 0.0f;
        #pragma unroll
        for (int off = (BT / 32) / 2; off > 0; off >>= 1) {
            float m2 = __shfl_xor_sync(0xffffffffu, m, off);
            float sx = __shfl_xor_sync(0xffffffffu, s, off);
            float nm = fmaxf(m, m2);
            s = s * exp2f((m - nm) * L2E) + sx * exp2f((m2 - nm) * L2E);
            m = nm;
        }
        if (lane == 0) {
            float lse = m + logf(s);
            float xt  = r[tgt[row]];
            g_row_loss[row] = lse - xt - log_scale;   // -(x_t - lse + log_scale)
            __threadfence();
            unsigned int v = atomicAdd(&g_done, 1u);
            s_last = (v == (unsigned int)(N - 1)) ? 1 : 0;
        }
    }
    __syncthreads();

    // ---- Last block to finish performs the deterministic final mean. ----
    if (s_last) {
        __threadfence();   // acquire all blocks' g_row_loss stores
        float acc = 0.0f;
        for (int j = tid; j < N; j += BT)
            acc += g_row_loss[j];

        #pragma unroll
        for (int off = 16; off > 0; off >>= 1)
            acc += __shfl_xor_sync(0xffffffffu, acc, off);

        __shared__ float w[BT / 32];
        if (lane == 0) w[warp] = acc;
        __syncthreads();
        if (warp == 0) {
            acc = (lane < BT / 32) ? w[lane] : 0.0f;
            #pragma unroll
            for (int off = (BT / 32) / 2; off > 0; off >>= 1)
                acc += __shfl_xor_sync(0xffffffffu, acc, off);
            if (lane == 0) {
                out[0] = acc / (float)N;
                g_done = 0;   // reset for next graph replay
            }
        }
    }
}

extern "C" void kernel_launch(void* const* d_in, const int* in_sizes, int n_in,
                              void* d_out, int out_size)
{
    const float* x   = (const float*)d_in[0];
    const int*   tgt = (const int*)d_in[1];
    float*       out = (float*)d_out;

    const int N = in_sizes[1];              // 4096 rows
    const int V = in_sizes[0] / N;          // 50257 classes

    const float ALPHA = 0.154f;
    const float scale = 1.0f - ALPHA + ALPHA / (float)V;
    const float log_scale = logf(scale);

    sce_fused_kernel<<<N, BT>>>(x, tgt, N, V, log_scale, out);
}